// round 3
// baseline (speedup 1.0000x reference)
#include <cuda_runtime.h>
#include <cstdint>
#include <cstddef>

// Problem constants
constexpr int VOCAB = 32000;
constexpr int DIM   = 1024;
constexpr int BITS  = 15;
constexpr int ROWS  = 4096;   // 4 * 1024
constexpr int KDIM  = 1024;

// GEMM tiling
constexpr int BM = 128;
constexpr int BN = 128;
constexpr int BK = 32;
constexpr int GEMM_THREADS = 256;
constexpr int STAGE_FLOATS_A = BM * BK;   // 4096 floats = 16KB
constexpr int STAGE_FLOATS_B = BN * BK;   // 16KB
constexpr int SMEM_BYTES = 2 * (STAGE_FLOATS_A + STAGE_FLOATS_B) * 4;  // 64KB

// ---------------------------------------------------------------------------
// Kernel 1: id_emb (row gather) + bit_emb (±1 bits @ weight_bit)
// ---------------------------------------------------------------------------
__global__ void embed_kernel(const int* __restrict__ ids,
                             const float* __restrict__ weight,
                             const float* __restrict__ weight_bit,
                             float* __restrict__ id_emb,
                             float* __restrict__ bit_emb) {
    int r = blockIdx.x;
    int id = ids[r];
    id = min(max(id, 0), VOCAB - 1);
    int d = threadIdx.x * 4;

    float4 w = *reinterpret_cast<const float4*>(weight + (size_t)id * DIM + d);
    *reinterpret_cast<float4*>(id_emb + (size_t)r * DIM + d) = w;

    float4 acc = make_float4(0.f, 0.f, 0.f, 0.f);
#pragma unroll
    for (int k = 0; k < BITS; ++k) {
        // bits array index k corresponds to bit position (BITS-1-k), MSB first
        float s = ((id >> (BITS - 1 - k)) & 1) ? 1.f : -1.f;
        float4 wb = *reinterpret_cast<const float4*>(weight_bit + k * DIM + d);
        acc.x = fmaf(s, wb.x, acc.x);
        acc.y = fmaf(s, wb.y, acc.y);
        acc.z = fmaf(s, wb.z, acc.z);
        acc.w = fmaf(s, wb.w, acc.w);
    }
    *reinterpret_cast<float4*>(bit_emb + (size_t)r * DIM + d) = acc;
}

// ---------------------------------------------------------------------------
// Kernel 2: logit = tensor[4096,1024] @ weight[32000,1024]^T
//           3xTF32 split precision (hi*hi + hi*lo + lo*hi)
// ---------------------------------------------------------------------------
__device__ __forceinline__ void cp16(unsigned saddr, const void* gaddr) {
    asm volatile("cp.async.cg.shared.global [%0], [%1], 16;\n"
                 :: "r"(saddr), "l"(gaddr) : "memory");
}
__device__ __forceinline__ void ldsm4(unsigned addr, unsigned& r0, unsigned& r1,
                                      unsigned& r2, unsigned& r3) {
    asm volatile("ldmatrix.sync.aligned.m8n8.x4.shared.b16 {%0,%1,%2,%3}, [%4];"
                 : "=r"(r0), "=r"(r1), "=r"(r2), "=r"(r3) : "r"(addr));
}
__device__ __forceinline__ unsigned cvt_tf32(unsigned x) {
    unsigned y;
    asm volatile("cvt.rna.tf32.f32 %0, %1;" : "=r"(y) : "r"(x));
    return y;
}
// split fp32 (as bits) into tf32 hi + tf32 lo
__device__ __forceinline__ void split_tf32(unsigned x, unsigned& hi, unsigned& lo) {
    hi = cvt_tf32(x);
    float resid = __uint_as_float(x) - __uint_as_float(hi);
    lo = cvt_tf32(__float_as_uint(resid));
}
__device__ __forceinline__ void mma_tf32(float* c, const unsigned* a, const unsigned* b) {
    asm volatile(
        "mma.sync.aligned.m16n8k8.row.col.f32.tf32.tf32.f32 "
        "{%0,%1,%2,%3}, {%4,%5,%6,%7}, {%8,%9}, {%0,%1,%2,%3};"
        : "+f"(c[0]), "+f"(c[1]), "+f"(c[2]), "+f"(c[3])
        : "r"(a[0]), "r"(a[1]), "r"(a[2]), "r"(a[3]), "r"(b[0]), "r"(b[1]));
}

// swizzled float offset within one [rows x 32] tile: row*32 + (chunk ^ (row&7))*4
__device__ __forceinline__ unsigned swz_fo(int row, int ch) {
    return (unsigned)((row << 5) + ((ch ^ (row & 7)) << 2));
}

__global__ __launch_bounds__(GEMM_THREADS, 2)
void gemm_tf32_kernel(const float* __restrict__ A,   // [4096,1024]
                      const float* __restrict__ B,   // [32000,1024]
                      float* __restrict__ C) {       // [4096,32000]
    extern __shared__ float smem[];
    unsigned sbase = (unsigned)__cvta_generic_to_shared(smem);
    // layout: As0 | As1 | Bs0 | Bs1  (16KB each)
    const unsigned aOff[2] = { 0u, (unsigned)(STAGE_FLOATS_A * 4) };
    const unsigned bOff[2] = { (unsigned)(2 * STAGE_FLOATS_A * 4),
                               (unsigned)(2 * STAGE_FLOATS_A * 4 + STAGE_FLOATS_B * 4) };

    int tid  = threadIdx.x;
    int warp = tid >> 5, lane = tid & 31;
    int wm = warp >> 2;       // 0..1  (64 rows each)
    int wn = warp & 3;        // 0..3  (32 cols each)

    int bm0 = blockIdx.x * BM;    // m tile (x fastest -> good B reuse per wave)
    int bn0 = blockIdx.y * BN;

    const float* Ag = A + (size_t)bm0 * KDIM;
    const float* Bg = B + (size_t)bn0 * KDIM;

    float acc[4][4][4];
#pragma unroll
    for (int mt = 0; mt < 4; ++mt)
#pragma unroll
        for (int nt = 0; nt < 4; ++nt)
#pragma unroll
            for (int i = 0; i < 4; ++i) acc[mt][nt][i] = 0.f;

    const int NK = KDIM / BK;   // 32

    // ---- prologue: load stage 0
    {
        int k0 = 0;
#pragma unroll
        for (int j = 0; j < 4; ++j) {
            int c = tid + (j << 8);
            int row = c >> 3, kc = c & 7;
            cp16(sbase + aOff[0] + (swz_fo(row, kc) << 2),
                 Ag + (size_t)row * KDIM + k0 + (kc << 2));
            cp16(sbase + bOff[0] + (swz_fo(row, kc) << 2),
                 Bg + (size_t)row * KDIM + k0 + (kc << 2));
        }
        asm volatile("cp.async.commit_group;" ::: "memory");
    }

    for (int kt = 0; kt < NK; ++kt) {
        int cur = kt & 1;
        if (kt + 1 < NK) {
            int nxt = (kt + 1) & 1;
            int k0 = (kt + 1) * BK;
#pragma unroll
            for (int j = 0; j < 4; ++j) {
                int c = tid + (j << 8);
                int row = c >> 3, kc = c & 7;
                cp16(sbase + aOff[nxt] + (swz_fo(row, kc) << 2),
                     Ag + (size_t)row * KDIM + k0 + (kc << 2));
                cp16(sbase + bOff[nxt] + (swz_fo(row, kc) << 2),
                     Bg + (size_t)row * KDIM + k0 + (kc << 2));
            }
            asm volatile("cp.async.commit_group;" ::: "memory");
            asm volatile("cp.async.wait_group 1;" ::: "memory");
        } else {
            asm volatile("cp.async.wait_group 0;" ::: "memory");
        }
        __syncthreads();

        unsigned aB = sbase + aOff[cur];
        unsigned bB = sbase + bOff[cur];

#pragma unroll
        for (int kk = 0; kk < 4; ++kk) {
            // A fragments: load + split into hi/lo (kept live across nt loop)
            unsigned aHi[4][4], aLo[4][4];
#pragma unroll
            for (int mt = 0; mt < 4; ++mt) {
                int mat = lane >> 3;
                int row = wm * 64 + mt * 16 + ((mat & 1) << 3) + (lane & 7);
                int ch  = 2 * kk + (mat >> 1);
                unsigned r[4];
                ldsm4(aB + (swz_fo(row, ch) << 2), r[0], r[1], r[2], r[3]);
#pragma unroll
                for (int i = 0; i < 4; ++i)
                    split_tf32(r[i], aHi[mt][i], aLo[mt][i]);
            }
            // B fragments: process one 16-col pair at a time (keeps regs low)
#pragma unroll
            for (int p = 0; p < 2; ++p) {
                int mat = lane >> 3;
                int row = wn * 32 + p * 16 + ((mat >> 1) << 3) + (lane & 7);
                int ch  = 2 * kk + (mat & 1);
                unsigned r0, r1, r2, r3;
                ldsm4(bB + (swz_fo(row, ch) << 2), r0, r1, r2, r3);
                unsigned bHi[2][2], bLo[2][2];
                split_tf32(r0, bHi[0][0], bLo[0][0]);
                split_tf32(r1, bHi[0][1], bLo[0][1]);
                split_tf32(r2, bHi[1][0], bLo[1][0]);
                split_tf32(r3, bHi[1][1], bLo[1][1]);
#pragma unroll
                for (int q = 0; q < 2; ++q) {
                    int nt = 2 * p + q;
#pragma unroll
                    for (int mt = 0; mt < 4; ++mt) {
                        mma_tf32(acc[mt][nt], aHi[mt], bLo[q]);  // hi*lo
                        mma_tf32(acc[mt][nt], aLo[mt], bHi[q]);  // lo*hi
                        mma_tf32(acc[mt][nt], aHi[mt], bHi[q]);  // hi*hi
                    }
                }
            }
        }
        __syncthreads();
    }

    // ---- epilogue
#pragma unroll
    for (int mt = 0; mt < 4; ++mt) {
        int r0 = bm0 + wm * 64 + mt * 16 + (lane >> 2);
#pragma unroll
        for (int nt = 0; nt < 4; ++nt) {
            int c0 = bn0 + wn * 32 + nt * 8 + ((lane & 3) << 1);
            *reinterpret_cast<float2*>(C + (size_t)r0 * VOCAB + c0) =
                make_float2(acc[mt][nt][0], acc[mt][nt][1]);
            *reinterpret_cast<float2*>(C + (size_t)(r0 + 8) * VOCAB + c0) =
                make_float2(acc[mt][nt][2], acc[mt][nt][3]);
        }
    }
}

// ---------------------------------------------------------------------------
// Kernel 3: logit_w = softmax(logit) @ vocab_bits  (single-pass online)
//   s_k = sum_{v with bit set} exp(x_v - m);  out_k = 2*s_k/Z - 1
//   v = i*256 + tid: bits 0..7 fixed per thread, bits 8..14 from i (0..124)
// ---------------------------------------------------------------------------
__global__ void softmax_bits_kernel(const float* __restrict__ logit,
                                    float* __restrict__ out) {
    int row = blockIdx.x;
    const float* x = logit + (size_t)row * VOCAB;
    int tid = threadIdx.x;

    float m = -1e30f, z = 0.f;
    float sh[7] = {0.f, 0.f, 0.f, 0.f, 0.f, 0.f, 0.f};

    for (int i = 0; i < VOCAB / 256; ++i) {   // 125 iterations
        float v = __ldg(x + (i << 8) + tid);
        if (v > m) {
            float sc = __expf(m - v);
            z *= sc;
#pragma unroll
            for (int j = 0; j < 7; ++j) sh[j] *= sc;
            m = v;
        }
        float e = __expf(v - m);
        z += e;
#pragma unroll
        for (int j = 0; j < 7; ++j)
            if ((i >> j) & 1) sh[j] += e;
    }

    // expand to full 15-bit state (MSB-first output ordering)
    float s[15];
#pragma unroll
    for (int k = 0; k < 7; ++k) s[k] = sh[6 - k];        // positions 14..8
#pragma unroll
    for (int p = 0; p < 8; ++p)                           // positions 7..0
        s[14 - p] = ((tid >> p) & 1) ? z : 0.f;

    // warp-level reduce (m, z, s[15])
#pragma unroll
    for (int off = 16; off > 0; off >>= 1) {
        float m2 = __shfl_down_sync(0xffffffffu, m, off);
        float z2 = __shfl_down_sync(0xffffffffu, z, off);
        float s2[15];
#pragma unroll
        for (int k = 0; k < 15; ++k) s2[k] = __shfl_down_sync(0xffffffffu, s[k], off);
        float M  = fmaxf(m, m2);
        float f1 = __expf(m - M), f2 = __expf(m2 - M);
        z = z * f1 + z2 * f2;
#pragma unroll
        for (int k = 0; k < 15; ++k) s[k] = s[k] * f1 + s2[k] * f2;
        m = M;
    }

    __shared__ float red[8][17];
    int warp = tid >> 5, lane = tid & 31;
    if (lane == 0) {
        red[warp][0] = m; red[warp][1] = z;
#pragma unroll
        for (int k = 0; k < 15; ++k) red[warp][2 + k] = s[k];
    }
    __syncthreads();
    if (warp == 0) {
        if (lane < 8) {
            m = red[lane][0]; z = red[lane][1];
#pragma unroll
            for (int k = 0; k < 15; ++k) s[k] = red[lane][2 + k];
        } else {
            m = -1e30f; z = 0.f;
#pragma unroll
            for (int k = 0; k < 15; ++k) s[k] = 0.f;
        }
#pragma unroll
        for (int off = 4; off > 0; off >>= 1) {
            float m2 = __shfl_down_sync(0xffffffffu, m, off);
            float z2 = __shfl_down_sync(0xffffffffu, z, off);
            float s2[15];
#pragma unroll
            for (int k = 0; k < 15; ++k) s2[k] = __shfl_down_sync(0xffffffffu, s[k], off);
            float M  = fmaxf(m, m2);
            float f1 = __expf(m - M), f2 = __expf(m2 - M);
            z = z * f1 + z2 * f2;
#pragma unroll
            for (int k = 0; k < 15; ++k) s[k] = s[k] * f1 + s2[k] * f2;
            m = M;
        }
        if (lane == 0) {
            float inv = 1.f / z;
#pragma unroll
            for (int k = 0; k < 15; ++k)
                out[(size_t)row * 15 + k] = 2.f * s[k] * inv - 1.f;
        }
    }
}

// ---------------------------------------------------------------------------
// launch
// ---------------------------------------------------------------------------
extern "C" void kernel_launch(void* const* d_in, const int* in_sizes, int n_in,
                              void* d_out, int out_size) {
    const int*   ids        = (const int*)d_in[0];
    const float* tensor     = (const float*)d_in[1];
    const float* weight     = (const float*)d_in[2];
    const float* weight_bit = (const float*)d_in[3];

    float* out     = (float*)d_out;
    float* id_emb  = out;
    float* bit_emb = id_emb + (size_t)ROWS * DIM;
    float* logit   = bit_emb + (size_t)ROWS * DIM;
    float* logit_w = logit + (size_t)ROWS * VOCAB;

    embed_kernel<<<ROWS, 256>>>(ids, weight, weight_bit, id_emb, bit_emb);

    static bool attr_set = false;
    if (!attr_set) {
        cudaFuncSetAttribute(gemm_tf32_kernel,
                             cudaFuncAttributeMaxDynamicSharedMemorySize, SMEM_BYTES);
        attr_set = true;
    }
    dim3 grid(ROWS / BM, VOCAB / BN);   // (32, 250), m fastest
    gemm_tf32_kernel<<<grid, GEMM_THREADS, SMEM_BYTES>>>(tensor, weight, logit);

    softmax_bits_kernel<<<ROWS, 256>>>(logit, logit_w);
}

// round 8
// speedup vs baseline: 1.7673x; 1.7673x over previous
#include <cuda_runtime.h>
#include <cuda_bf16.h>
#include <cstdint>
#include <cstddef>

// Problem constants
constexpr int VOCAB = 32000;
constexpr int DIM   = 1024;
constexpr int BITS  = 15;
constexpr int ROWS  = 4096;   // 4 * 1024
constexpr int KDIM  = 1024;
constexpr int K3    = 3 * KDIM;   // 3072: [hi|hi|lo] x [hi|lo|hi]

// Pre-converted bf16 operands (scratch; static device arrays are legal)
__device__ __nv_bfloat16 g_A3[(size_t)ROWS * K3];    // 25 MB
__device__ __nv_bfloat16 g_B3[(size_t)VOCAB * K3];   // 197 MB

// GEMM tiling: 128x256x64, 512 threads (16 warps: 2m x 8n, warp tile 64x32)
constexpr int BM = 128;
constexpr int BN = 256;
constexpr int BK = 64;                    // bf16 -> 128B rows (SW128-style)
constexpr int GEMM_THREADS = 512;
constexpr int A_PART = BM * BK * 2;       // 16384 B
constexpr int B_PART = BN * BK * 2;       // 32768 B
constexpr int STAGE  = A_PART + B_PART;   // 49152 B
constexpr int GEMM_SMEM = 2 * STAGE;      // 98304 B

// ---------------------------------------------------------------------------
// helpers
// ---------------------------------------------------------------------------
__device__ __forceinline__ void cp16(unsigned saddr, const void* gaddr) {
    asm volatile("cp.async.cg.shared.global [%0], [%1], 16;\n"
                 :: "r"(saddr), "l"(gaddr) : "memory");
}
__device__ __forceinline__ void ldsm4(unsigned addr, unsigned& r0, unsigned& r1,
                                      unsigned& r2, unsigned& r3) {
    asm volatile("ldmatrix.sync.aligned.m8n8.x4.shared.b16 {%0,%1,%2,%3}, [%4];"
                 : "=r"(r0), "=r"(r1), "=r"(r2), "=r"(r3) : "r"(addr));
}
__device__ __forceinline__ void mma_bf16(float* c, const unsigned* a, const unsigned* b) {
    asm volatile(
        "mma.sync.aligned.m16n8k16.row.col.f32.bf16.bf16.f32 "
        "{%0,%1,%2,%3}, {%4,%5,%6,%7}, {%8,%9}, {%0,%1,%2,%3};"
        : "+f"(c[0]), "+f"(c[1]), "+f"(c[2]), "+f"(c[3])
        : "r"(a[0]), "r"(a[1]), "r"(a[2]), "r"(a[3]), "r"(b[0]), "r"(b[1]));
}
// byte offset within a [rows x 64bf16] tile, swizzled (128B rows, 16B chunks)
__device__ __forceinline__ unsigned swz(int row, int ch) {
    return (unsigned)((row << 7) + ((ch ^ (row & 7)) << 4));
}
// split two fp32 into bf16x2 hi (e low half, o high half) and bf16x2 lo
__device__ __forceinline__ void cvt_pair(float e, float o, uint32_t& h, uint32_t& l) {
    asm volatile("cvt.rn.bf16x2.f32 %0, %1, %2;" : "=r"(h) : "f"(o), "f"(e));
    float he = __uint_as_float(h << 16);
    float ho = __uint_as_float(h & 0xFFFF0000u);
    float le = e - he;
    float lq = o - ho;
    asm volatile("cvt.rn.bf16x2.f32 %0, %1, %2;" : "=r"(l) : "f"(lq), "f"(le));
}

// ---------------------------------------------------------------------------
// Convert kernels: fp32 -> bf16 hi/lo, K-concatenated layouts
//   A3 row: [hi(0:1024) | hi(1024:2048) | lo(2048:3072)]
//   B3 row: [hi(0:1024) | lo(1024:2048) | hi(2048:3072)]
// ---------------------------------------------------------------------------
__global__ void convertA_kernel(const float* __restrict__ A) {
    int r = blockIdx.x;
    int k = threadIdx.x * 4;
    float4 f = *reinterpret_cast<const float4*>(A + (size_t)r * KDIM + k);
    uint32_t h0, l0, h1, l1;
    cvt_pair(f.x, f.y, h0, l0);
    cvt_pair(f.z, f.w, h1, l1);
    __nv_bfloat16* dst = g_A3 + (size_t)r * K3;
    *reinterpret_cast<uint2*>(dst + k)        = make_uint2(h0, h1);
    *reinterpret_cast<uint2*>(dst + KDIM + k) = make_uint2(h0, h1);
    *reinterpret_cast<uint2*>(dst + 2 * KDIM + k) = make_uint2(l0, l1);
}
__global__ void convertB_kernel(const float* __restrict__ B) {
    int r = blockIdx.x;
    int k = threadIdx.x * 4;
    float4 f = *reinterpret_cast<const float4*>(B + (size_t)r * KDIM + k);
    uint32_t h0, l0, h1, l1;
    cvt_pair(f.x, f.y, h0, l0);
    cvt_pair(f.z, f.w, h1, l1);
    __nv_bfloat16* dst = g_B3 + (size_t)r * K3;
    *reinterpret_cast<uint2*>(dst + k)        = make_uint2(h0, h1);
    *reinterpret_cast<uint2*>(dst + KDIM + k) = make_uint2(l0, l1);
    *reinterpret_cast<uint2*>(dst + 2 * KDIM + k) = make_uint2(h0, h1);
}

// ---------------------------------------------------------------------------
// GEMM: logit[4096,32000] = A3[4096,3072] @ B3[32000,3072]^T   (bf16 HMMA)
// ---------------------------------------------------------------------------
__global__ __launch_bounds__(GEMM_THREADS, 1)
void gemm_bf16_kernel(float* __restrict__ C) {
    extern __shared__ char smem[];
    unsigned sbase;
    asm("{ .reg .u64 t; cvta.to.shared.u64 t, %1; cvt.u32.u64 %0, t; }"
        : "=r"(sbase) : "l"(smem));

    int tid  = threadIdx.x;
    int warp = tid >> 5, lane = tid & 31;
    int wm = warp >> 3;        // 0..1  (64 rows each)
    int wn = warp & 7;         // 0..7  (32 cols each)

    int bm0 = blockIdx.x * BM;
    int bn0 = blockIdx.y * BN;

    const __nv_bfloat16* Ag = g_A3 + (size_t)bm0 * K3;
    const __nv_bfloat16* Bg = g_B3 + (size_t)bn0 * K3;

    float acc[4][4][4];
#pragma unroll
    for (int mt = 0; mt < 4; ++mt)
#pragma unroll
        for (int nt = 0; nt < 4; ++nt)
#pragma unroll
            for (int i = 0; i < 4; ++i) acc[mt][nt][i] = 0.f;

    const int NK = K3 / BK;    // 48

    // stage fill: 3072 16B-chunks (A:1024, B:2048), 6 per thread
    auto fill = [&](int st, int kt) {
        unsigned sA = sbase + st * STAGE;
        unsigned sB = sA + A_PART;
        int kofs = kt * BK;
#pragma unroll
        for (int j = 0; j < 6; ++j) {
            int c = tid + j * GEMM_THREADS;
            if (c < 1024) {
                int row = c >> 3, ch = c & 7;
                cp16(sA + swz(row, ch),
                     Ag + (size_t)row * K3 + kofs + ch * 8);
            } else {
                int c2 = c - 1024;
                int row = c2 >> 3, ch = c2 & 7;
                cp16(sB + swz(row, ch),
                     Bg + (size_t)row * K3 + kofs + ch * 8);
            }
        }
        asm volatile("cp.async.commit_group;" ::: "memory");
    };

    fill(0, 0);

    for (int kt = 0; kt < NK; ++kt) {
        int cur = kt & 1;
        if (kt + 1 < NK) {
            fill((kt + 1) & 1, kt + 1);
            asm volatile("cp.async.wait_group 1;" ::: "memory");
        } else {
            asm volatile("cp.async.wait_group 0;" ::: "memory");
        }
        __syncthreads();

        unsigned aB = sbase + cur * STAGE;
        unsigned bB = aB + A_PART;

#pragma unroll
        for (int kk = 0; kk < 4; ++kk) {   // k16 steps within BK=64
            int mat = lane >> 3;
            unsigned aF[4][4];
#pragma unroll
            for (int mt = 0; mt < 4; ++mt) {
                int row = wm * 64 + mt * 16 + ((mat & 1) << 3) + (lane & 7);
                int ch  = 2 * kk + (mat >> 1);
                ldsm4(aB + swz(row, ch), aF[mt][0], aF[mt][1], aF[mt][2], aF[mt][3]);
            }
            unsigned bF[4][2];
#pragma unroll
            for (int p = 0; p < 2; ++p) {
                int row = wn * 32 + p * 16 + ((mat >> 1) << 3) + (lane & 7);
                int ch  = 2 * kk + (mat & 1);
                unsigned r0, r1, r2, r3;
                ldsm4(bB + swz(row, ch), r0, r1, r2, r3);
                bF[2 * p][0] = r0; bF[2 * p][1] = r1;
                bF[2 * p + 1][0] = r2; bF[2 * p + 1][1] = r3;
            }
#pragma unroll
            for (int mt = 0; mt < 4; ++mt)
#pragma unroll
                for (int nt = 0; nt < 4; ++nt)
                    mma_bf16(acc[mt][nt], aF[mt], bF[nt]);
        }
        __syncthreads();
    }

    // epilogue
#pragma unroll
    for (int mt = 0; mt < 4; ++mt) {
        int r0 = bm0 + wm * 64 + mt * 16 + (lane >> 2);
#pragma unroll
        for (int nt = 0; nt < 4; ++nt) {
            int c0 = bn0 + wn * 32 + nt * 8 + ((lane & 3) << 1);
            *reinterpret_cast<float2*>(C + (size_t)r0 * VOCAB + c0) =
                make_float2(acc[mt][nt][0], acc[mt][nt][1]);
            *reinterpret_cast<float2*>(C + (size_t)(r0 + 8) * VOCAB + c0) =
                make_float2(acc[mt][nt][2], acc[mt][nt][3]);
        }
    }
}

// ---------------------------------------------------------------------------
// Kernel 1: id_emb (row gather) + bit_emb (±1 bits @ weight_bit)
// ---------------------------------------------------------------------------
__global__ void embed_kernel(const int* __restrict__ ids,
                             const float* __restrict__ weight,
                             const float* __restrict__ weight_bit,
                             float* __restrict__ id_emb,
                             float* __restrict__ bit_emb) {
    int r = blockIdx.x;
    int id = ids[r];
    id = min(max(id, 0), VOCAB - 1);
    int d = threadIdx.x * 4;

    float4 w = *reinterpret_cast<const float4*>(weight + (size_t)id * DIM + d);
    *reinterpret_cast<float4*>(id_emb + (size_t)r * DIM + d) = w;

    float4 acc = make_float4(0.f, 0.f, 0.f, 0.f);
#pragma unroll
    for (int k = 0; k < BITS; ++k) {
        float s = ((id >> (BITS - 1 - k)) & 1) ? 1.f : -1.f;
        float4 wb = *reinterpret_cast<const float4*>(weight_bit + k * DIM + d);
        acc.x = fmaf(s, wb.x, acc.x);
        acc.y = fmaf(s, wb.y, acc.y);
        acc.z = fmaf(s, wb.z, acc.z);
        acc.w = fmaf(s, wb.w, acc.w);
    }
    *reinterpret_cast<float4*>(bit_emb + (size_t)r * DIM + d) = acc;
}

// ---------------------------------------------------------------------------
// Kernel 3: logit_w = softmax(logit) @ vocab_bits  (single-pass online)
// ---------------------------------------------------------------------------
__global__ void softmax_bits_kernel(const float* __restrict__ logit,
                                    float* __restrict__ out) {
    int row = blockIdx.x;
    const float* x = logit + (size_t)row * VOCAB;
    int tid = threadIdx.x;

    float m = -1e30f, z = 0.f;
    float sh[7] = {0.f, 0.f, 0.f, 0.f, 0.f, 0.f, 0.f};

    for (int i = 0; i < VOCAB / 256; ++i) {   // 125 iterations
        float v = __ldg(x + (i << 8) + tid);
        if (v > m) {
            float sc = __expf(m - v);
            z *= sc;
#pragma unroll
            for (int j = 0; j < 7; ++j) sh[j] *= sc;
            m = v;
        }
        float e = __expf(v - m);
        z += e;
#pragma unroll
        for (int j = 0; j < 7; ++j)
            if ((i >> j) & 1) sh[j] += e;
    }

    float s[15];
#pragma unroll
    for (int k = 0; k < 7; ++k) s[k] = sh[6 - k];        // positions 14..8
#pragma unroll
    for (int p = 0; p < 8; ++p)                           // positions 7..0
        s[14 - p] = ((tid >> p) & 1) ? z : 0.f;

#pragma unroll
    for (int off = 16; off > 0; off >>= 1) {
        float m2 = __shfl_down_sync(0xffffffffu, m, off);
        float z2 = __shfl_down_sync(0xffffffffu, z, off);
        float s2[15];
#pragma unroll
        for (int k = 0; k < 15; ++k) s2[k] = __shfl_down_sync(0xffffffffu, s[k], off);
        float M  = fmaxf(m, m2);
        float f1 = __expf(m - M), f2 = __expf(m2 - M);
        z = z * f1 + z2 * f2;
#pragma unroll
        for (int k = 0; k < 15; ++k) s[k] = s[k] * f1 + s2[k] * f2;
        m = M;
    }

    __shared__ float red[8][17];
    int warp = tid >> 5, lane = tid & 31;
    if (lane == 0) {
        red[warp][0] = m; red[warp][1] = z;
#pragma unroll
        for (int k = 0; k < 15; ++k) red[warp][2 + k] = s[k];
    }
    __syncthreads();
    if (warp == 0) {
        if (lane < 8) {
            m = red[lane][0]; z = red[lane][1];
#pragma unroll
            for (int k = 0; k < 15; ++k) s[k] = red[lane][2 + k];
        } else {
            m = -1e30f; z = 0.f;
#pragma unroll
            for (int k = 0; k < 15; ++k) s[k] = 0.f;
        }
#pragma unroll
        for (int off = 4; off > 0; off >>= 1) {
            float m2 = __shfl_down_sync(0xffffffffu, m, off);
            float z2 = __shfl_down_sync(0xffffffffu, z, off);
            float s2[15];
#pragma unroll
            for (int k = 0; k < 15; ++k) s2[k] = __shfl_down_sync(0xffffffffu, s[k], off);
            float M  = fmaxf(m, m2);
            float f1 = __expf(m - M), f2 = __expf(m2 - M);
            z = z * f1 + z2 * f2;
#pragma unroll
            for (int k = 0; k < 15; ++k) s[k] = s[k] * f1 + s2[k] * f2;
            m = M;
        }
        if (lane == 0) {
            float inv = 1.f / z;
#pragma unroll
            for (int k = 0; k < 15; ++k)
                out[(size_t)row * 15 + k] = 2.f * s[k] * inv - 1.f;
        }
    }
}

// ---------------------------------------------------------------------------
// launch
// ---------------------------------------------------------------------------
extern "C" void kernel_launch(void* const* d_in, const int* in_sizes, int n_in,
                              void* d_out, int out_size) {
    const int*   ids        = (const int*)d_in[0];
    const float* tensor     = (const float*)d_in[1];
    const float* weight     = (const float*)d_in[2];
    const float* weight_bit = (const float*)d_in[3];

    float* out     = (float*)d_out;
    float* id_emb  = out;
    float* bit_emb = id_emb + (size_t)ROWS * DIM;
    float* logit   = bit_emb + (size_t)ROWS * DIM;
    float* logit_w = logit + (size_t)ROWS * VOCAB;

    embed_kernel<<<ROWS, 256>>>(ids, weight, weight_bit, id_emb, bit_emb);

    convertA_kernel<<<ROWS, 256>>>(tensor);
    convertB_kernel<<<VOCAB, 256>>>(weight);

    static bool attr_set = false;
    if (!attr_set) {
        cudaFuncSetAttribute(gemm_bf16_kernel,
                             cudaFuncAttributeMaxDynamicSharedMemorySize, GEMM_SMEM);
        attr_set = true;
    }
    dim3 grid(ROWS / BM, VOCAB / BN);   // (32, 125), m fastest for B reuse
    gemm_bf16_kernel<<<grid, GEMM_THREADS, GEMM_SMEM>>>(logit);

    softmax_bits_kernel<<<ROWS, 256>>>(logit, logit_w);
}

// round 11
// speedup vs baseline: 1.9571x; 1.1074x over previous
#include <cuda_runtime.h>
#include <cuda_bf16.h>
#include <cstdint>
#include <cstddef>

// Problem constants
constexpr int VOCAB = 32000;
constexpr int DIM   = 1024;
constexpr int BITS  = 15;
constexpr int ROWS  = 4096;   // 4 * 1024
constexpr int KDIM  = 1024;
constexpr int K3    = 3 * KDIM;   // 3072: [hi|hi|lo] x [hi|lo|hi]

// Pre-converted bf16 operands (scratch; static device arrays are legal)
__device__ __nv_bfloat16 g_A3[(size_t)ROWS * K3];    // 25 MB
__device__ __nv_bfloat16 g_B3[(size_t)VOCAB * K3];   // 197 MB

// GEMM tiling: 128x256x64, 512 threads (16 warps: 2m x 8n, warp tile 64x32)
constexpr int BM = 128;
constexpr int BN = 256;
constexpr int BK = 64;                    // bf16 -> 128B rows (SW128-style)
constexpr int GEMM_THREADS = 512;
constexpr int A_PART = BM * BK * 2;       // 16384 B
constexpr int B_PART = BN * BK * 2;       // 32768 B
constexpr int STAGE  = A_PART + B_PART;   // 49152 B
constexpr int NSTAGE = 3;
constexpr int GEMM_SMEM = NSTAGE * STAGE; // 147456 B

// ---------------------------------------------------------------------------
// helpers
// ---------------------------------------------------------------------------
__device__ __forceinline__ void cp16(unsigned saddr, const void* gaddr) {
    asm volatile("cp.async.cg.shared.global [%0], [%1], 16;\n"
                 :: "r"(saddr), "l"(gaddr) : "memory");
}
__device__ __forceinline__ void ldsm4(unsigned addr, unsigned& r0, unsigned& r1,
                                      unsigned& r2, unsigned& r3) {
    asm volatile("ldmatrix.sync.aligned.m8n8.x4.shared.b16 {%0,%1,%2,%3}, [%4];"
                 : "=r"(r0), "=r"(r1), "=r"(r2), "=r"(r3) : "r"(addr));
}
__device__ __forceinline__ void mma_bf16(float* c, const unsigned* a, const unsigned* b) {
    asm volatile(
        "mma.sync.aligned.m16n8k16.row.col.f32.bf16.bf16.f32 "
        "{%0,%1,%2,%3}, {%4,%5,%6,%7}, {%8,%9}, {%0,%1,%2,%3};"
        : "+f"(c[0]), "+f"(c[1]), "+f"(c[2]), "+f"(c[3])
        : "r"(a[0]), "r"(a[1]), "r"(a[2]), "r"(a[3]), "r"(b[0]), "r"(b[1]));
}
// byte offset within a [rows x 64bf16] tile, swizzled (128B rows, 16B chunks)
__device__ __forceinline__ unsigned swz(int row, int ch) {
    return (unsigned)((row << 7) + ((ch ^ (row & 7)) << 4));
}
// split two fp32 into bf16x2 hi (e low half, o high half) and bf16x2 lo
__device__ __forceinline__ void cvt_pair(float e, float o, uint32_t& h, uint32_t& l) {
    asm volatile("cvt.rn.bf16x2.f32 %0, %1, %2;" : "=r"(h) : "f"(o), "f"(e));
    float he = __uint_as_float(h << 16);
    float ho = __uint_as_float(h & 0xFFFF0000u);
    float le = e - he;
    float lq = o - ho;
    asm volatile("cvt.rn.bf16x2.f32 %0, %1, %2;" : "=r"(l) : "f"(lq), "f"(le));
}

// ---------------------------------------------------------------------------
// Convert kernels: fp32 -> bf16 hi/lo, K-concatenated layouts
//   A3 row: [hi(0:1024) | hi(1024:2048) | lo(2048:3072)]
//   B3 row: [hi(0:1024) | lo(1024:2048) | hi(2048:3072)]
// ---------------------------------------------------------------------------
__global__ void convertA_kernel(const float* __restrict__ A) {
    int r = blockIdx.x;
    int k = threadIdx.x * 4;
    float4 f = *reinterpret_cast<const float4*>(A + (size_t)r * KDIM + k);
    uint32_t h0, l0, h1, l1;
    cvt_pair(f.x, f.y, h0, l0);
    cvt_pair(f.z, f.w, h1, l1);
    __nv_bfloat16* dst = g_A3 + (size_t)r * K3;
    *reinterpret_cast<uint2*>(dst + k)            = make_uint2(h0, h1);
    *reinterpret_cast<uint2*>(dst + KDIM + k)     = make_uint2(h0, h1);
    *reinterpret_cast<uint2*>(dst + 2 * KDIM + k) = make_uint2(l0, l1);
}
__global__ void convertB_kernel(const float* __restrict__ B) {
    int r = blockIdx.x;
    int k = threadIdx.x * 4;
    float4 f = *reinterpret_cast<const float4*>(B + (size_t)r * KDIM + k);
    uint32_t h0, l0, h1, l1;
    cvt_pair(f.x, f.y, h0, l0);
    cvt_pair(f.z, f.w, h1, l1);
    __nv_bfloat16* dst = g_B3 + (size_t)r * K3;
    *reinterpret_cast<uint2*>(dst + k)            = make_uint2(h0, h1);
    *reinterpret_cast<uint2*>(dst + KDIM + k)     = make_uint2(l0, l1);
    *reinterpret_cast<uint2*>(dst + 2 * KDIM + k) = make_uint2(h0, h1);
}

// ---------------------------------------------------------------------------
// GEMM: logit[4096,32000] = A3[4096,3072] @ B3[32000,3072]^T   (bf16 HMMA)
// 3-stage cp.async pipeline, one barrier per k-iteration
// ---------------------------------------------------------------------------
__global__ __launch_bounds__(GEMM_THREADS, 1)
void gemm_bf16_kernel(float* __restrict__ C) {
    extern __shared__ char smem[];
    unsigned sbase;
    asm("{ .reg .u64 t; cvta.to.shared.u64 t, %1; cvt.u32.u64 %0, t; }"
        : "=r"(sbase) : "l"(smem));

    int tid  = threadIdx.x;
    int warp = tid >> 5, lane = tid & 31;
    int wm = warp >> 3;        // 0..1  (64 rows each)
    int wn = warp & 7;         // 0..7  (32 cols each)

    int bm0 = blockIdx.x * BM;
    int bn0 = blockIdx.y * BN;

    const __nv_bfloat16* Ag = g_A3 + (size_t)bm0 * K3;
    const __nv_bfloat16* Bg = g_B3 + (size_t)bn0 * K3;

    float acc[4][4][4];
#pragma unroll
    for (int mt = 0; mt < 4; ++mt)
#pragma unroll
        for (int nt = 0; nt < 4; ++nt)
#pragma unroll
            for (int i = 0; i < 4; ++i) acc[mt][nt][i] = 0.f;

    const int NK = K3 / BK;    // 48

    // stage fill: 3072 16B-chunks (A:1024, B:2048), 6 per thread
    auto fill = [&](int st, int kt) {
        unsigned sA = sbase + st * STAGE;
        unsigned sB = sA + A_PART;
        int kofs = kt * BK;
#pragma unroll
        for (int j = 0; j < 6; ++j) {
            int c = tid + j * GEMM_THREADS;
            if (c < 1024) {
                int row = c >> 3, ch = c & 7;
                cp16(sA + swz(row, ch),
                     Ag + (size_t)row * K3 + kofs + ch * 8);
            } else {
                int c2 = c - 1024;
                int row = c2 >> 3, ch = c2 & 7;
                cp16(sB + swz(row, ch),
                     Bg + (size_t)row * K3 + kofs + ch * 8);
            }
        }
    };

    // prologue: stages 0,1 (groups 0,1)
    fill(0, 0);
    asm volatile("cp.async.commit_group;" ::: "memory");
    fill(1, 1);
    asm volatile("cp.async.commit_group;" ::: "memory");

    int cur = 0;               // stage of kt
    for (int kt = 0; kt < NK; ++kt) {
        asm volatile("cp.async.wait_group 1;" ::: "memory");
        __syncthreads();

        // prefetch kt+2 into the stage consumed at kt-1 (safe after barrier)
        if (kt + 2 < NK) {
            int st = cur + 2; if (st >= NSTAGE) st -= NSTAGE;
            fill(st, kt + 2);
        }
        asm volatile("cp.async.commit_group;" ::: "memory");

        unsigned aB = sbase + cur * STAGE;
        unsigned bB = aB + A_PART;

#pragma unroll
        for (int kk = 0; kk < 4; ++kk) {   // k16 steps within BK=64
            int mat = lane >> 3;
            unsigned aF[4][4];
#pragma unroll
            for (int mt = 0; mt < 4; ++mt) {
                int row = wm * 64 + mt * 16 + ((mat & 1) << 3) + (lane & 7);
                int ch  = 2 * kk + (mat >> 1);
                ldsm4(aB + swz(row, ch), aF[mt][0], aF[mt][1], aF[mt][2], aF[mt][3]);
            }
            unsigned bF[4][2];
#pragma unroll
            for (int p = 0; p < 2; ++p) {
                int row = wn * 32 + p * 16 + ((mat >> 1) << 3) + (lane & 7);
                int ch  = 2 * kk + (mat & 1);
                unsigned r0, r1, r2, r3;
                ldsm4(bB + swz(row, ch), r0, r1, r2, r3);
                bF[2 * p][0] = r0; bF[2 * p][1] = r1;
                bF[2 * p + 1][0] = r2; bF[2 * p + 1][1] = r3;
            }
#pragma unroll
            for (int mt = 0; mt < 4; ++mt)
#pragma unroll
                for (int nt = 0; nt < 4; ++nt)
                    mma_bf16(acc[mt][nt], aF[mt], bF[nt]);
        }
        if (++cur == NSTAGE) cur = 0;
    }

    // epilogue
#pragma unroll
    for (int mt = 0; mt < 4; ++mt) {
        int r0 = bm0 + wm * 64 + mt * 16 + (lane >> 2);
#pragma unroll
        for (int nt = 0; nt < 4; ++nt) {
            int c0 = bn0 + wn * 32 + nt * 8 + ((lane & 3) << 1);
            *reinterpret_cast<float2*>(C + (size_t)r0 * VOCAB + c0) =
                make_float2(acc[mt][nt][0], acc[mt][nt][1]);
            *reinterpret_cast<float2*>(C + (size_t)(r0 + 8) * VOCAB + c0) =
                make_float2(acc[mt][nt][2], acc[mt][nt][3]);
        }
    }
}

// ---------------------------------------------------------------------------
// Kernel 1: id_emb (row gather) + bit_emb (±1 bits @ weight_bit)
// ---------------------------------------------------------------------------
__global__ void embed_kernel(const int* __restrict__ ids,
                             const float* __restrict__ weight,
                             const float* __restrict__ weight_bit,
                             float* __restrict__ id_emb,
                             float* __restrict__ bit_emb) {
    int r = blockIdx.x;
    int id = ids[r];
    id = min(max(id, 0), VOCAB - 1);
    int d = threadIdx.x * 4;

    float4 w = *reinterpret_cast<const float4*>(weight + (size_t)id * DIM + d);
    *reinterpret_cast<float4*>(id_emb + (size_t)r * DIM + d) = w;

    float4 acc = make_float4(0.f, 0.f, 0.f, 0.f);
#pragma unroll
    for (int k = 0; k < BITS; ++k) {
        float s = ((id >> (BITS - 1 - k)) & 1) ? 1.f : -1.f;
        float4 wb = *reinterpret_cast<const float4*>(weight_bit + k * DIM + d);
        acc.x = fmaf(s, wb.x, acc.x);
        acc.y = fmaf(s, wb.y, acc.y);
        acc.z = fmaf(s, wb.z, acc.z);
        acc.w = fmaf(s, wb.w, acc.w);
    }
    *reinterpret_cast<float4*>(bit_emb + (size_t)r * DIM + d) = acc;
}

// ---------------------------------------------------------------------------
// Kernel 3: logit_w = softmax(logit) @ vocab_bits
// Two-pass (row max, then FMA-pipe exp). v = o*2048 + tid*8 + c:
//   bits 0..2 = c (12-add tree per 8), bits 3..10 = tid (free),
//   bits 11..14 = o (predicated adds of the 8-group subtotal).
// ---------------------------------------------------------------------------
__device__ __forceinline__ float exp_fma(float x, float mlog) {
    // exp(x - m) = 2^(x*log2e - mlog), all on fma/alu pipes
    float y = fmaf(x, 1.4426950408889634f, -mlog);
    y = fmaxf(y, -120.f);
    float t  = __fadd_rn(y, 12582912.f);          // rint via magic
    float yn = __fadd_rn(t, -12582912.f);
    float f  = y - yn;                             // [-0.5, 0.5]
    float p = fmaf(f, 0.0013333558f, 0.0096181291f);
    p = fmaf(f, p, 0.0555041087f);
    p = fmaf(f, p, 0.2402265070f);
    p = fmaf(f, p, 0.6931471806f);
    p = fmaf(f, p, 1.0f);
    int nb = (__float_as_int(t) - 0x4B400000) << 23;
    return __int_as_float(__float_as_int(p) + nb);
}

__global__ void softmax_bits_kernel(const float* __restrict__ logit,
                                    float* __restrict__ out) {
    int row = blockIdx.x;
    const float* x = logit + (size_t)row * VOCAB;
    int tid = threadIdx.x;          // 256
    int warp = tid >> 5, lane = tid & 31;

    __shared__ float smax[8];
    __shared__ float sred[8][16];
    __shared__ float sfin[16];
    __shared__ float sm;

    // ---- pass 1: row max
    float mx = -3.4e38f;
#pragma unroll 4
    for (int o = 0; o < 16; ++o) {
        if (o == 15 && tid >= 160) continue;   // 32000 boundary
        const float* p = x + o * 2048 + tid * 8;
        float4 a = *reinterpret_cast<const float4*>(p);
        float4 b = *reinterpret_cast<const float4*>(p + 4);
        mx = fmaxf(mx, fmaxf(fmaxf(fmaxf(a.x, a.y), fmaxf(a.z, a.w)),
                             fmaxf(fmaxf(b.x, b.y), fmaxf(b.z, b.w))));
    }
#pragma unroll
    for (int off = 16; off > 0; off >>= 1)
        mx = fmaxf(mx, __shfl_xor_sync(0xffffffffu, mx, off));
    if (lane == 0) smax[warp] = mx;
    __syncthreads();
    if (tid == 0) {
        float m = smax[0];
#pragma unroll
        for (int w = 1; w < 8; ++w) m = fmaxf(m, smax[w]);
        sm = m * 1.4426950408889634f;
    }
    __syncthreads();
    float mlog = sm;

    // ---- pass 2: exp + structured bit sums
    float zt = 0.f, sb0 = 0.f, sb1 = 0.f, sb2 = 0.f;
    float so[4] = {0.f, 0.f, 0.f, 0.f};
#pragma unroll 4
    for (int o = 0; o < 16; ++o) {
        if (o == 15 && tid >= 160) continue;
        const float* p = x + o * 2048 + tid * 8;
        float4 a = *reinterpret_cast<const float4*>(p);
        float4 b = *reinterpret_cast<const float4*>(p + 4);
        float e0 = exp_fma(a.x, mlog), e1 = exp_fma(a.y, mlog);
        float e2 = exp_fma(a.z, mlog), e3 = exp_fma(a.w, mlog);
        float e4 = exp_fma(b.x, mlog), e5 = exp_fma(b.y, mlog);
        float e6 = exp_fma(b.z, mlog), e7 = exp_fma(b.w, mlog);
        float t01 = e0 + e1, t23 = e2 + e3, t45 = e4 + e5, t67 = e6 + e7;
        float b2 = t45 + t67;
        float z8 = (t01 + t23) + b2;
        float b1 = t23 + t67;
        float b0 = (e1 + e3) + (e5 + e7);
        sb0 += b0; sb1 += b1; sb2 += b2; zt += z8;
        if (o & 1) so[0] += z8;
        if (o & 2) so[1] += z8;
        if (o & 4) so[2] += z8;
        if (o & 8) so[3] += z8;
    }

    // build per-thread s[0..14] (bit position order) + z at s[15]
    float s[16];
    s[0] = sb0; s[1] = sb1; s[2] = sb2;
#pragma unroll
    for (int pbit = 0; pbit < 8; ++pbit)
        s[3 + pbit] = ((tid >> pbit) & 1) ? zt : 0.f;
    s[11] = so[0]; s[12] = so[1]; s[13] = so[2]; s[14] = so[3];
    s[15] = zt;

    // block reduce (sum of 16 floats)
#pragma unroll
    for (int off = 16; off > 0; off >>= 1)
#pragma unroll
        for (int k = 0; k < 16; ++k)
            s[k] += __shfl_xor_sync(0xffffffffu, s[k], off);
    if (lane == 0)
#pragma unroll
        for (int k = 0; k < 16; ++k) sred[warp][k] = s[k];
    __syncthreads();
    if (tid < 16) {
        float v = 0.f;
#pragma unroll
        for (int w = 0; w < 8; ++w) v += sred[w][tid];
        sfin[tid] = v;
    }
    __syncthreads();
    if (tid < 15) {
        float Z = sfin[15];
        // output MSB-first: out[k] uses bit position 14-k
        out[(size_t)row * 15 + tid] = 2.f * sfin[14 - tid] / Z - 1.f;
    }
}

// ---------------------------------------------------------------------------
// launch
// ---------------------------------------------------------------------------
extern "C" void kernel_launch(void* const* d_in, const int* in_sizes, int n_in,
                              void* d_out, int out_size) {
    const int*   ids        = (const int*)d_in[0];
    const float* tensor     = (const float*)d_in[1];
    const float* weight     = (const float*)d_in[2];
    const float* weight_bit = (const float*)d_in[3];

    float* out     = (float*)d_out;
    float* id_emb  = out;
    float* bit_emb = id_emb + (size_t)ROWS * DIM;
    float* logit   = bit_emb + (size_t)ROWS * DIM;
    float* logit_w = logit + (size_t)ROWS * VOCAB;

    embed_kernel<<<ROWS, 256>>>(ids, weight, weight_bit, id_emb, bit_emb);

    convertA_kernel<<<ROWS, 256>>>(tensor);
    convertB_kernel<<<VOCAB, 256>>>(weight);

    static bool attr_set = false;
    if (!attr_set) {
        cudaFuncSetAttribute(gemm_bf16_kernel,
                             cudaFuncAttributeMaxDynamicSharedMemorySize, GEMM_SMEM);
        attr_set = true;
    }
    dim3 grid(ROWS / BM, VOCAB / BN);   // (32, 125), m fastest for B reuse
    gemm_bf16_kernel<<<grid, GEMM_THREADS, GEMM_SMEM>>>(logit);

    softmax_bits_kernel<<<ROWS, 256>>>(logit, logit_w);
}

// round 12
// speedup vs baseline: 2.0878x; 1.0668x over previous
#include <cuda_runtime.h>
#include <cuda_bf16.h>
#include <cstdint>
#include <cstddef>

// Problem constants
constexpr int VOCAB = 32000;
constexpr int DIM   = 1024;
constexpr int BITS  = 15;
constexpr int ROWS  = 4096;   // 4 * 1024
constexpr int KDIM  = 1024;
constexpr int K3    = 3 * KDIM;   // 3072: [hi|hi|lo] x [hi|lo|hi]

// Pre-converted bf16 operands (scratch; static device arrays are legal)
__device__ __nv_bfloat16 g_A3[(size_t)ROWS * K3];    // 25 MB
__device__ __nv_bfloat16 g_B3[(size_t)VOCAB * K3];   // 197 MB

// GEMM tiling: 128x128x64, 256 threads (8 warps: 2m x 4n, warp tile 64x32)
// -> 2 CTAs/SM (96KB smem, ~100 regs/thread) so barriers interleave
constexpr int BM = 128;
constexpr int BN = 128;
constexpr int BK = 64;                    // bf16 -> 128B rows (SW128-style)
constexpr int GEMM_THREADS = 256;
constexpr int A_PART = BM * BK * 2;       // 16384 B
constexpr int B_PART = BN * BK * 2;       // 16384 B
constexpr int STAGE  = A_PART + B_PART;   // 32768 B
constexpr int NSTAGE = 3;
constexpr int GEMM_SMEM = NSTAGE * STAGE; // 98304 B

// ---------------------------------------------------------------------------
// helpers
// ---------------------------------------------------------------------------
__device__ __forceinline__ void cp16(unsigned saddr, const void* gaddr) {
    asm volatile("cp.async.cg.shared.global [%0], [%1], 16;\n"
                 :: "r"(saddr), "l"(gaddr) : "memory");
}
__device__ __forceinline__ void ldsm4(unsigned addr, unsigned& r0, unsigned& r1,
                                      unsigned& r2, unsigned& r3) {
    asm volatile("ldmatrix.sync.aligned.m8n8.x4.shared.b16 {%0,%1,%2,%3}, [%4];"
                 : "=r"(r0), "=r"(r1), "=r"(r2), "=r"(r3) : "r"(addr));
}
__device__ __forceinline__ void mma_bf16(float* c, const unsigned* a, const unsigned* b) {
    asm volatile(
        "mma.sync.aligned.m16n8k16.row.col.f32.bf16.bf16.f32 "
        "{%0,%1,%2,%3}, {%4,%5,%6,%7}, {%8,%9}, {%0,%1,%2,%3};"
        : "+f"(c[0]), "+f"(c[1]), "+f"(c[2]), "+f"(c[3])
        : "r"(a[0]), "r"(a[1]), "r"(a[2]), "r"(a[3]), "r"(b[0]), "r"(b[1]));
}
// byte offset within a [rows x 64bf16] tile, swizzled (128B rows, 16B chunks)
__device__ __forceinline__ unsigned swz(int row, int ch) {
    return (unsigned)((row << 7) + ((ch ^ (row & 7)) << 4));
}
// split two fp32 into bf16x2 hi (e low half, o high half) and bf16x2 lo
__device__ __forceinline__ void cvt_pair(float e, float o, uint32_t& h, uint32_t& l) {
    asm volatile("cvt.rn.bf16x2.f32 %0, %1, %2;" : "=r"(h) : "f"(o), "f"(e));
    float he = __uint_as_float(h << 16);
    float ho = __uint_as_float(h & 0xFFFF0000u);
    float le = e - he;
    float lq = o - ho;
    asm volatile("cvt.rn.bf16x2.f32 %0, %1, %2;" : "=r"(l) : "f"(lq), "f"(le));
}

// ---------------------------------------------------------------------------
// Convert kernels: fp32 -> bf16 hi/lo, K-concatenated layouts
//   A3 row: [hi(0:1024) | hi(1024:2048) | lo(2048:3072)]
//   B3 row: [hi(0:1024) | lo(1024:2048) | hi(2048:3072)]
// ---------------------------------------------------------------------------
__global__ void convertA_kernel(const float* __restrict__ A) {
    int r = blockIdx.x;
    int k = threadIdx.x * 4;
    float4 f = *reinterpret_cast<const float4*>(A + (size_t)r * KDIM + k);
    uint32_t h0, l0, h1, l1;
    cvt_pair(f.x, f.y, h0, l0);
    cvt_pair(f.z, f.w, h1, l1);
    __nv_bfloat16* dst = g_A3 + (size_t)r * K3;
    *reinterpret_cast<uint2*>(dst + k)            = make_uint2(h0, h1);
    *reinterpret_cast<uint2*>(dst + KDIM + k)     = make_uint2(h0, h1);
    *reinterpret_cast<uint2*>(dst + 2 * KDIM + k) = make_uint2(l0, l1);
}
__global__ void convertB_kernel(const float* __restrict__ B) {
    int r = blockIdx.x;
    int k = threadIdx.x * 4;
    float4 f = *reinterpret_cast<const float4*>(B + (size_t)r * KDIM + k);
    uint32_t h0, l0, h1, l1;
    cvt_pair(f.x, f.y, h0, l0);
    cvt_pair(f.z, f.w, h1, l1);
    __nv_bfloat16* dst = g_B3 + (size_t)r * K3;
    *reinterpret_cast<uint2*>(dst + k)            = make_uint2(h0, h1);
    *reinterpret_cast<uint2*>(dst + KDIM + k)     = make_uint2(l0, l1);
    *reinterpret_cast<uint2*>(dst + 2 * KDIM + k) = make_uint2(h0, h1);
}

// ---------------------------------------------------------------------------
// GEMM: logit[4096,32000] = A3[4096,3072] @ B3[32000,3072]^T   (bf16 HMMA)
// 3-stage cp.async pipeline, one barrier per k-iteration, 2 CTAs/SM
// ---------------------------------------------------------------------------
__global__ __launch_bounds__(GEMM_THREADS, 2)
void gemm_bf16_kernel(float* __restrict__ C) {
    extern __shared__ char smem[];
    unsigned sbase;
    asm("{ .reg .u64 t; cvta.to.shared.u64 t, %1; cvt.u32.u64 %0, t; }"
        : "=r"(sbase) : "l"(smem));

    int tid  = threadIdx.x;
    int warp = tid >> 5, lane = tid & 31;
    int wm = warp >> 2;        // 0..1  (64 rows each)
    int wn = warp & 3;         // 0..3  (32 cols each)

    int bm0 = blockIdx.x * BM;
    int bn0 = blockIdx.y * BN;

    const __nv_bfloat16* Ag = g_A3 + (size_t)bm0 * K3;
    const __nv_bfloat16* Bg = g_B3 + (size_t)bn0 * K3;

    float acc[4][4][4];
#pragma unroll
    for (int mt = 0; mt < 4; ++mt)
#pragma unroll
        for (int nt = 0; nt < 4; ++nt)
#pragma unroll
            for (int i = 0; i < 4; ++i) acc[mt][nt][i] = 0.f;

    const int NK = K3 / BK;    // 48

    // stage fill: 2048 16B-chunks (A:1024, B:1024), 8 per thread
    auto fill = [&](int st, int kt) {
        unsigned sA = sbase + st * STAGE;
        unsigned sB = sA + A_PART;
        int kofs = kt * BK;
#pragma unroll
        for (int j = 0; j < 8; ++j) {
            int c = tid + j * GEMM_THREADS;
            if (c < 1024) {
                int row = c >> 3, ch = c & 7;
                cp16(sA + swz(row, ch),
                     Ag + (size_t)row * K3 + kofs + ch * 8);
            } else {
                int c2 = c - 1024;
                int row = c2 >> 3, ch = c2 & 7;
                cp16(sB + swz(row, ch),
                     Bg + (size_t)row * K3 + kofs + ch * 8);
            }
        }
    };

    // prologue: stages 0,1 (groups 0,1)
    fill(0, 0);
    asm volatile("cp.async.commit_group;" ::: "memory");
    fill(1, 1);
    asm volatile("cp.async.commit_group;" ::: "memory");

    int cur = 0;               // stage of kt
    for (int kt = 0; kt < NK; ++kt) {
        asm volatile("cp.async.wait_group 1;" ::: "memory");
        __syncthreads();

        // prefetch kt+2 into the stage consumed at kt-1 (safe after barrier)
        if (kt + 2 < NK) {
            int st = cur + 2; if (st >= NSTAGE) st -= NSTAGE;
            fill(st, kt + 2);
        }
        asm volatile("cp.async.commit_group;" ::: "memory");

        unsigned aB = sbase + cur * STAGE;
        unsigned bB = aB + A_PART;

#pragma unroll
        for (int kk = 0; kk < 4; ++kk) {   // k16 steps within BK=64
            int mat = lane >> 3;
            unsigned aF[4][4];
#pragma unroll
            for (int mt = 0; mt < 4; ++mt) {
                int row = wm * 64 + mt * 16 + ((mat & 1) << 3) + (lane & 7);
                int ch  = 2 * kk + (mat >> 1);
                ldsm4(aB + swz(row, ch), aF[mt][0], aF[mt][1], aF[mt][2], aF[mt][3]);
            }
            unsigned bF[4][2];
#pragma unroll
            for (int p = 0; p < 2; ++p) {
                int row = wn * 32 + p * 16 + ((mat >> 1) << 3) + (lane & 7);
                int ch  = 2 * kk + (mat & 1);
                unsigned r0, r1, r2, r3;
                ldsm4(bB + swz(row, ch), r0, r1, r2, r3);
                bF[2 * p][0] = r0; bF[2 * p][1] = r1;
                bF[2 * p + 1][0] = r2; bF[2 * p + 1][1] = r3;
            }
#pragma unroll
            for (int mt = 0; mt < 4; ++mt)
#pragma unroll
                for (int nt = 0; nt < 4; ++nt)
                    mma_bf16(acc[mt][nt], aF[mt], bF[nt]);
        }
        if (++cur == NSTAGE) cur = 0;
    }

    // epilogue
#pragma unroll
    for (int mt = 0; mt < 4; ++mt) {
        int r0 = bm0 + wm * 64 + mt * 16 + (lane >> 2);
#pragma unroll
        for (int nt = 0; nt < 4; ++nt) {
            int c0 = bn0 + wn * 32 + nt * 8 + ((lane & 3) << 1);
            *reinterpret_cast<float2*>(C + (size_t)r0 * VOCAB + c0) =
                make_float2(acc[mt][nt][0], acc[mt][nt][1]);
            *reinterpret_cast<float2*>(C + (size_t)(r0 + 8) * VOCAB + c0) =
                make_float2(acc[mt][nt][2], acc[mt][nt][3]);
        }
    }
}

// ---------------------------------------------------------------------------
// Kernel 1: id_emb (row gather) + bit_emb (±1 bits @ weight_bit)
// ---------------------------------------------------------------------------
__global__ void embed_kernel(const int* __restrict__ ids,
                             const float* __restrict__ weight,
                             const float* __restrict__ weight_bit,
                             float* __restrict__ id_emb,
                             float* __restrict__ bit_emb) {
    int r = blockIdx.x;
    int id = ids[r];
    id = min(max(id, 0), VOCAB - 1);
    int d = threadIdx.x * 4;

    float4 w = *reinterpret_cast<const float4*>(weight + (size_t)id * DIM + d);
    *reinterpret_cast<float4*>(id_emb + (size_t)r * DIM + d) = w;

    float4 acc = make_float4(0.f, 0.f, 0.f, 0.f);
#pragma unroll
    for (int k = 0; k < BITS; ++k) {
        float s = ((id >> (BITS - 1 - k)) & 1) ? 1.f : -1.f;
        float4 wb = *reinterpret_cast<const float4*>(weight_bit + k * DIM + d);
        acc.x = fmaf(s, wb.x, acc.x);
        acc.y = fmaf(s, wb.y, acc.y);
        acc.z = fmaf(s, wb.z, acc.z);
        acc.w = fmaf(s, wb.w, acc.w);
    }
    *reinterpret_cast<float4*>(bit_emb + (size_t)r * DIM + d) = acc;
}

// ---------------------------------------------------------------------------
// Kernel 3: logit_w = softmax(logit) @ vocab_bits
// Two-pass (row max, then FMA-pipe exp). v = o*2048 + tid*8 + c:
//   bits 0..2 = c (12-add tree per 8), bits 3..10 = tid (free),
//   bits 11..14 = o (predicated adds of the 8-group subtotal).
// ---------------------------------------------------------------------------
__device__ __forceinline__ float exp_fma(float x, float mlog) {
    // exp(x - m) = 2^(x*log2e - mlog), all on fma/alu pipes
    float y = fmaf(x, 1.4426950408889634f, -mlog);
    y = fmaxf(y, -120.f);
    float t  = __fadd_rn(y, 12582912.f);          // rint via magic
    float yn = __fadd_rn(t, -12582912.f);
    float f  = y - yn;                             // [-0.5, 0.5]
    float p = fmaf(f, 0.0013333558f, 0.0096181291f);
    p = fmaf(f, p, 0.0555041087f);
    p = fmaf(f, p, 0.2402265070f);
    p = fmaf(f, p, 0.6931471806f);
    p = fmaf(f, p, 1.0f);
    int nb = (__float_as_int(t) - 0x4B400000) << 23;
    return __int_as_float(__float_as_int(p) + nb);
}

__global__ void softmax_bits_kernel(const float* __restrict__ logit,
                                    float* __restrict__ out) {
    int row = blockIdx.x;
    const float* x = logit + (size_t)row * VOCAB;
    int tid = threadIdx.x;          // 256
    int warp = tid >> 5, lane = tid & 31;

    __shared__ float smax[8];
    __shared__ float sred[8][16];
    __shared__ float sfin[16];
    __shared__ float sm;

    // ---- pass 1: row max
    float mx = -3.4e38f;
#pragma unroll 4
    for (int o = 0; o < 16; ++o) {
        if (o == 15 && tid >= 160) continue;   // 32000 boundary
        const float* p = x + o * 2048 + tid * 8;
        float4 a = *reinterpret_cast<const float4*>(p);
        float4 b = *reinterpret_cast<const float4*>(p + 4);
        mx = fmaxf(mx, fmaxf(fmaxf(fmaxf(a.x, a.y), fmaxf(a.z, a.w)),
                             fmaxf(fmaxf(b.x, b.y), fmaxf(b.z, b.w))));
    }
#pragma unroll
    for (int off = 16; off > 0; off >>= 1)
        mx = fmaxf(mx, __shfl_xor_sync(0xffffffffu, mx, off));
    if (lane == 0) smax[warp] = mx;
    __syncthreads();
    if (tid == 0) {
        float m = smax[0];
#pragma unroll
        for (int w = 1; w < 8; ++w) m = fmaxf(m, smax[w]);
        sm = m * 1.4426950408889634f;
    }
    __syncthreads();
    float mlog = sm;

    // ---- pass 2: exp + structured bit sums
    float zt = 0.f, sb0 = 0.f, sb1 = 0.f, sb2 = 0.f;
    float so[4] = {0.f, 0.f, 0.f, 0.f};
#pragma unroll 4
    for (int o = 0; o < 16; ++o) {
        if (o == 15 && tid >= 160) continue;
        const float* p = x + o * 2048 + tid * 8;
        float4 a = *reinterpret_cast<const float4*>(p);
        float4 b = *reinterpret_cast<const float4*>(p + 4);
        float e0 = exp_fma(a.x, mlog), e1 = exp_fma(a.y, mlog);
        float e2 = exp_fma(a.z, mlog), e3 = exp_fma(a.w, mlog);
        float e4 = exp_fma(b.x, mlog), e5 = exp_fma(b.y, mlog);
        float e6 = exp_fma(b.z, mlog), e7 = exp_fma(b.w, mlog);
        float t01 = e0 + e1, t23 = e2 + e3, t45 = e4 + e5, t67 = e6 + e7;
        float b2 = t45 + t67;
        float z8 = (t01 + t23) + b2;
        float b1 = t23 + t67;
        float b0 = (e1 + e3) + (e5 + e7);
        sb0 += b0; sb1 += b1; sb2 += b2; zt += z8;
        if (o & 1) so[0] += z8;
        if (o & 2) so[1] += z8;
        if (o & 4) so[2] += z8;
        if (o & 8) so[3] += z8;
    }

    // build per-thread s[0..14] (bit position order) + z at s[15]
    float s[16];
    s[0] = sb0; s[1] = sb1; s[2] = sb2;
#pragma unroll
    for (int pbit = 0; pbit < 8; ++pbit)
        s[3 + pbit] = ((tid >> pbit) & 1) ? zt : 0.f;
    s[11] = so[0]; s[12] = so[1]; s[13] = so[2]; s[14] = so[3];
    s[15] = zt;

    // block reduce (sum of 16 floats)
#pragma unroll
    for (int off = 16; off > 0; off >>= 1)
#pragma unroll
        for (int k = 0; k < 16; ++k)
            s[k] += __shfl_xor_sync(0xffffffffu, s[k], off);
    if (lane == 0)
#pragma unroll
        for (int k = 0; k < 16; ++k) sred[warp][k] = s[k];
    __syncthreads();
    if (tid < 16) {
        float v = 0.f;
#pragma unroll
        for (int w = 0; w < 8; ++w) v += sred[w][tid];
        sfin[tid] = v;
    }
    __syncthreads();
    if (tid < 15) {
        float Z = sfin[15];
        // output MSB-first: out[k] uses bit position 14-k
        out[(size_t)row * 15 + tid] = 2.f * sfin[14 - tid] / Z - 1.f;
    }
}

// ---------------------------------------------------------------------------
// launch
// ---------------------------------------------------------------------------
extern "C" void kernel_launch(void* const* d_in, const int* in_sizes, int n_in,
                              void* d_out, int out_size) {
    const int*   ids        = (const int*)d_in[0];
    const float* tensor     = (const float*)d_in[1];
    const float* weight     = (const float*)d_in[2];
    const float* weight_bit = (const float*)d_in[3];

    float* out     = (float*)d_out;
    float* id_emb  = out;
    float* bit_emb = id_emb + (size_t)ROWS * DIM;
    float* logit   = bit_emb + (size_t)ROWS * DIM;
    float* logit_w = logit + (size_t)ROWS * VOCAB;

    embed_kernel<<<ROWS, 256>>>(ids, weight, weight_bit, id_emb, bit_emb);

    convertA_kernel<<<ROWS, 256>>>(tensor);
    convertB_kernel<<<VOCAB, 256>>>(weight);

    static bool attr_set = false;
    if (!attr_set) {
        cudaFuncSetAttribute(gemm_bf16_kernel,
                             cudaFuncAttributeMaxDynamicSharedMemorySize, GEMM_SMEM);
        attr_set = true;
    }
    dim3 grid(ROWS / BM, VOCAB / BN);   // (32, 250), m fastest for B reuse
    gemm_bf16_kernel<<<grid, GEMM_THREADS, GEMM_SMEM>>>(logit);

    softmax_bits_kernel<<<ROWS, 256>>>(logit, logit_w);
}

// round 15
// speedup vs baseline: 2.1412x; 1.0256x over previous
#include <cuda_runtime.h>
#include <cuda_bf16.h>
#include <cstdint>
#include <cstddef>

// Problem constants
constexpr int VOCAB = 32000;
constexpr int DIM   = 1024;
constexpr int BITS  = 15;
constexpr int ROWS  = 4096;   // 4 * 1024
constexpr int KDIM  = 1024;
constexpr int K3    = 3 * KDIM;   // 3072: [hi|hi|lo] x [hi|lo|hi]

// Pre-converted bf16 operands (scratch; static device arrays are legal)
__device__ __nv_bfloat16 g_A3[(size_t)ROWS * K3];    // 25 MB
__device__ __nv_bfloat16 g_B3[(size_t)VOCAB * K3];   // 197 MB
// per-row logit max, order-preserving-encoded fp32 (filled by GEMM epilogue)
__device__ unsigned g_rowmax[ROWS];

// GEMM tiling: 128x128x64, 256 threads (8 warps: 2m x 4n, warp tile 64x32)
// -> 2 CTAs/SM (96KB smem, 128 regs/thread) so barriers interleave
constexpr int BM = 128;
constexpr int BN = 128;
constexpr int BK = 64;                    // bf16 -> 128B rows (SW128-style)
constexpr int GEMM_THREADS = 256;
constexpr int A_PART = BM * BK * 2;       // 16384 B
constexpr int B_PART = BN * BK * 2;       // 16384 B
constexpr int STAGE  = A_PART + B_PART;   // 32768 B
constexpr int NSTAGE = 3;
constexpr int GEMM_SMEM = NSTAGE * STAGE; // 98304 B

// ---------------------------------------------------------------------------
// helpers
// ---------------------------------------------------------------------------
__device__ __forceinline__ void cp16(unsigned saddr, const void* gaddr) {
    asm volatile("cp.async.cg.shared.global [%0], [%1], 16;\n"
                 :: "r"(saddr), "l"(gaddr) : "memory");
}
__device__ __forceinline__ void ldsm4(unsigned addr, unsigned& r0, unsigned& r1,
                                      unsigned& r2, unsigned& r3) {
    asm volatile("ldmatrix.sync.aligned.m8n8.x4.shared.b16 {%0,%1,%2,%3}, [%4];"
                 : "=r"(r0), "=r"(r1), "=r"(r2), "=r"(r3) : "r"(addr));
}
__device__ __forceinline__ void mma_bf16(float* c, const unsigned* a, const unsigned* b) {
    asm volatile(
        "mma.sync.aligned.m16n8k16.row.col.f32.bf16.bf16.f32 "
        "{%0,%1,%2,%3}, {%4,%5,%6,%7}, {%8,%9}, {%0,%1,%2,%3};"
        : "+f"(c[0]), "+f"(c[1]), "+f"(c[2]), "+f"(c[3])
        : "r"(a[0]), "r"(a[1]), "r"(a[2]), "r"(a[3]), "r"(b[0]), "r"(b[1]));
}
// byte offset within a [rows x 64bf16] tile, swizzled (128B rows, 16B chunks)
__device__ __forceinline__ unsigned swz(int row, int ch) {
    return (unsigned)((row << 7) + ((ch ^ (row & 7)) << 4));
}
// split two fp32 into bf16x2 hi (e low half, o high half) and bf16x2 lo
__device__ __forceinline__ void cvt_pair(float e, float o, uint32_t& h, uint32_t& l) {
    asm volatile("cvt.rn.bf16x2.f32 %0, %1, %2;" : "=r"(h) : "f"(o), "f"(e));
    float he = __uint_as_float(h << 16);
    float ho = __uint_as_float(h & 0xFFFF0000u);
    float le = e - he;
    float lq = o - ho;
    asm volatile("cvt.rn.bf16x2.f32 %0, %1, %2;" : "=r"(l) : "f"(lq), "f"(le));
}
// order-preserving float<->uint for atomicMax
__device__ __forceinline__ unsigned enc_ord(float f) {
    unsigned u = __float_as_uint(f);
    return (u & 0x80000000u) ? ~u : (u | 0x80000000u);
}
__device__ __forceinline__ float dec_ord(unsigned u) {
    return (u & 0x80000000u) ? __uint_as_float(u & 0x7fffffffu)
                             : __uint_as_float(~u);
}

// ---------------------------------------------------------------------------
// rowmax init
// ---------------------------------------------------------------------------
__global__ void rowmax_init_kernel() {
    g_rowmax[blockIdx.x * 256 + threadIdx.x] = 0u;   // below enc of any float
}

// ---------------------------------------------------------------------------
// Convert kernels: fp32 -> bf16 hi/lo, K-concatenated layouts
//   A3 row: [hi(0:1024) | hi(1024:2048) | lo(2048:3072)]
//   B3 row: [hi(0:1024) | lo(1024:2048) | hi(2048:3072)]
// ---------------------------------------------------------------------------
__global__ void convertA_kernel(const float* __restrict__ A) {
    int r = blockIdx.x;
    int k = threadIdx.x * 4;
    float4 f = *reinterpret_cast<const float4*>(A + (size_t)r * KDIM + k);
    uint32_t h0, l0, h1, l1;
    cvt_pair(f.x, f.y, h0, l0);
    cvt_pair(f.z, f.w, h1, l1);
    __nv_bfloat16* dst = g_A3 + (size_t)r * K3;
    *reinterpret_cast<uint2*>(dst + k)            = make_uint2(h0, h1);
    *reinterpret_cast<uint2*>(dst + KDIM + k)     = make_uint2(h0, h1);
    *reinterpret_cast<uint2*>(dst + 2 * KDIM + k) = make_uint2(l0, l1);
}
__global__ void convertB_kernel(const float* __restrict__ B) {
    int r = blockIdx.x;
    int k = threadIdx.x * 4;
    float4 f = *reinterpret_cast<const float4*>(B + (size_t)r * KDIM + k);
    uint32_t h0, l0, h1, l1;
    cvt_pair(f.x, f.y, h0, l0);
    cvt_pair(f.z, f.w, h1, l1);
    __nv_bfloat16* dst = g_B3 + (size_t)r * K3;
    *reinterpret_cast<uint2*>(dst + k)            = make_uint2(h0, h1);
    *reinterpret_cast<uint2*>(dst + KDIM + k)     = make_uint2(l0, l1);
    *reinterpret_cast<uint2*>(dst + 2 * KDIM + k) = make_uint2(h0, h1);
}

// ---------------------------------------------------------------------------
// GEMM: logit[4096,32000] = A3[4096,3072] @ B3[32000,3072]^T   (bf16 HMMA)
// 3-stage cp.async pipeline, 2 CTAs/SM, warp-parity kk stagger,
// fused per-row max (atomicMax) in the epilogue
// ---------------------------------------------------------------------------
__global__ __launch_bounds__(GEMM_THREADS, 2)
void gemm_bf16_kernel(float* __restrict__ C) {
    extern __shared__ char smem[];
    unsigned sbase;
    asm("{ .reg .u64 t; cvta.to.shared.u64 t, %1; cvt.u32.u64 %0, t; }"
        : "=r"(sbase) : "l"(smem));

    int tid  = threadIdx.x;
    int warp = tid >> 5, lane = tid & 31;
    int wm = warp >> 2;        // 0..1  (64 rows each)
    int wn = warp & 3;         // 0..3  (32 cols each)
    int krot = (warp & 1) << 1;   // de-phase LDSM bursts across warp parity

    int bm0 = blockIdx.x * BM;
    int bn0 = blockIdx.y * BN;

    const __nv_bfloat16* Ag = g_A3 + (size_t)bm0 * K3;
    const __nv_bfloat16* Bg = g_B3 + (size_t)bn0 * K3;

    float acc[4][4][4];
#pragma unroll
    for (int mt = 0; mt < 4; ++mt)
#pragma unroll
        for (int nt = 0; nt < 4; ++nt)
#pragma unroll
            for (int i = 0; i < 4; ++i) acc[mt][nt][i] = 0.f;

    const int NK = K3 / BK;    // 48

    // stage fill: 2048 16B-chunks (A:1024, B:1024), 8 per thread
    auto fill = [&](int st, int kt) {
        unsigned sA = sbase + st * STAGE;
        unsigned sB = sA + A_PART;
        int kofs = kt * BK;
#pragma unroll
        for (int j = 0; j < 8; ++j) {
            int c = tid + j * GEMM_THREADS;
            if (c < 1024) {
                int row = c >> 3, ch = c & 7;
                cp16(sA + swz(row, ch),
                     Ag + (size_t)row * K3 + kofs + ch * 8);
            } else {
                int c2 = c - 1024;
                int row = c2 >> 3, ch = c2 & 7;
                cp16(sB + swz(row, ch),
                     Bg + (size_t)row * K3 + kofs + ch * 8);
            }
        }
    };

    // prologue: stages 0,1 (groups 0,1)
    fill(0, 0);
    asm volatile("cp.async.commit_group;" ::: "memory");
    fill(1, 1);
    asm volatile("cp.async.commit_group;" ::: "memory");

    int cur = 0;               // stage of kt
    for (int kt = 0; kt < NK; ++kt) {
        asm volatile("cp.async.wait_group 1;" ::: "memory");
        __syncthreads();

        // prefetch kt+2 into the stage consumed at kt-1 (safe after barrier)
        if (kt + 2 < NK) {
            int st = cur + 2; if (st >= NSTAGE) st -= NSTAGE;
            fill(st, kt + 2);
        }
        asm volatile("cp.async.commit_group;" ::: "memory");

        unsigned aB = sbase + cur * STAGE;
        unsigned bB = aB + A_PART;

#pragma unroll
        for (int kx = 0; kx < 4; ++kx) {   // k16 steps within BK=64, staggered
            int kk = (kx + krot) & 3;
            int mat = lane >> 3;
            unsigned aF[4][4];
#pragma unroll
            for (int mt = 0; mt < 4; ++mt) {
                int row = wm * 64 + mt * 16 + ((mat & 1) << 3) + (lane & 7);
                int ch  = 2 * kk + (mat >> 1);
                ldsm4(aB + swz(row, ch), aF[mt][0], aF[mt][1], aF[mt][2], aF[mt][3]);
            }
            unsigned bF[4][2];
#pragma unroll
            for (int p = 0; p < 2; ++p) {
                int row = wn * 32 + p * 16 + ((mat >> 1) << 3) + (lane & 7);
                int ch  = 2 * kk + (mat & 1);
                unsigned r0, r1, r2, r3;
                ldsm4(bB + swz(row, ch), r0, r1, r2, r3);
                bF[2 * p][0] = r0; bF[2 * p][1] = r1;
                bF[2 * p + 1][0] = r2; bF[2 * p + 1][1] = r3;
            }
#pragma unroll
            for (int mt = 0; mt < 4; ++mt)
#pragma unroll
                for (int nt = 0; nt < 4; ++nt)
                    mma_bf16(acc[mt][nt], aF[mt], bF[nt]);
        }
        if (++cur == NSTAGE) cur = 0;
    }

    // epilogue: store + fused per-row max
#pragma unroll
    for (int mt = 0; mt < 4; ++mt) {
        int r0 = bm0 + wm * 64 + mt * 16 + (lane >> 2);
        float m0 = -3.4e38f, m1 = -3.4e38f;
#pragma unroll
        for (int nt = 0; nt < 4; ++nt) {
            int c0 = bn0 + wn * 32 + nt * 8 + ((lane & 3) << 1);
            *reinterpret_cast<float2*>(C + (size_t)r0 * VOCAB + c0) =
                make_float2(acc[mt][nt][0], acc[mt][nt][1]);
            *reinterpret_cast<float2*>(C + (size_t)(r0 + 8) * VOCAB + c0) =
                make_float2(acc[mt][nt][2], acc[mt][nt][3]);
            m0 = fmaxf(m0, fmaxf(acc[mt][nt][0], acc[mt][nt][1]));
            m1 = fmaxf(m1, fmaxf(acc[mt][nt][2], acc[mt][nt][3]));
        }
        // reduce within quad (lanes 4q..4q+3 share the same rows)
#pragma unroll
        for (int off = 1; off <= 2; off <<= 1) {
            m0 = fmaxf(m0, __shfl_xor_sync(0xffffffffu, m0, off));
            m1 = fmaxf(m1, __shfl_xor_sync(0xffffffffu, m1, off));
        }
        if ((lane & 3) == 0) {
            atomicMax(&g_rowmax[r0], enc_ord(m0));
            atomicMax(&g_rowmax[r0 + 8], enc_ord(m1));
        }
    }
}

// ---------------------------------------------------------------------------
// Kernel 1: id_emb (row gather) + bit_emb (±1 bits @ weight_bit)
// ---------------------------------------------------------------------------
__global__ void embed_kernel(const int* __restrict__ ids,
                             const float* __restrict__ weight,
                             const float* __restrict__ weight_bit,
                             float* __restrict__ id_emb,
                             float* __restrict__ bit_emb) {
    int r = blockIdx.x;
    int id = ids[r];
    id = min(max(id, 0), VOCAB - 1);
    int d = threadIdx.x * 4;

    float4 w = *reinterpret_cast<const float4*>(weight + (size_t)id * DIM + d);
    *reinterpret_cast<float4*>(id_emb + (size_t)r * DIM + d) = w;

    float4 acc = make_float4(0.f, 0.f, 0.f, 0.f);
#pragma unroll
    for (int k = 0; k < BITS; ++k) {
        float s = ((id >> (BITS - 1 - k)) & 1) ? 1.f : -1.f;
        float4 wb = *reinterpret_cast<const float4*>(weight_bit + k * DIM + d);
        acc.x = fmaf(s, wb.x, acc.x);
        acc.y = fmaf(s, wb.y, acc.y);
        acc.z = fmaf(s, wb.z, acc.z);
        acc.w = fmaf(s, wb.w, acc.w);
    }
    *reinterpret_cast<float4*>(bit_emb + (size_t)r * DIM + d) = acc;
}

// ---------------------------------------------------------------------------
// Kernel 3: logit_w = softmax(logit) @ vocab_bits
// Single exp pass (row max precomputed by GEMM epilogue). FMA-pipe exp.
// v = o*2048 + tid*8 + c: bits 0..2 from c, 3..10 from tid, 11..14 from o.
// ---------------------------------------------------------------------------
__device__ __forceinline__ float exp_fma(float x, float mlog) {
    // exp(x - m) = 2^(x*log2e - mlog), all on fma/alu pipes
    float y = fmaf(x, 1.4426950408889634f, -mlog);
    y = fmaxf(y, -120.f);
    float t  = __fadd_rn(y, 12582912.f);          // rint via magic
    float yn = __fadd_rn(t, -12582912.f);
    float f  = y - yn;                             // [-0.5, 0.5]
    float p = fmaf(f, 0.0013333558f, 0.0096181291f);
    p = fmaf(f, p, 0.0555041087f);
    p = fmaf(f, p, 0.2402265070f);
    p = fmaf(f, p, 0.6931471806f);
    p = fmaf(f, p, 1.0f);
    int nb = (__float_as_int(t) - 0x4B400000) << 23;
    return __int_as_float(__float_as_int(p) + nb);
}

__global__ void softmax_bits_kernel(const float* __restrict__ logit,
                                    float* __restrict__ out) {
    int row = blockIdx.x;
    const float* x = logit + (size_t)row * VOCAB;
    int tid = threadIdx.x;          // 256
    int warp = tid >> 5, lane = tid & 31;

    __shared__ float sred[8][16];
    __shared__ float sfin[16];

    float mlog = dec_ord(g_rowmax[row]) * 1.4426950408889634f;

    // ---- exp + structured bit sums
    float zt = 0.f, sb0 = 0.f, sb1 = 0.f, sb2 = 0.f;
    float so[4] = {0.f, 0.f, 0.f, 0.f};
#pragma unroll 4
    for (int o = 0; o < 16; ++o) {
        if (o == 15 && tid >= 160) continue;   // 32000 boundary
        const float* p = x + o * 2048 + tid * 8;
        float4 a = *reinterpret_cast<const float4*>(p);
        float4 b = *reinterpret_cast<const float4*>(p + 4);
        float e0 = exp_fma(a.x, mlog), e1 = exp_fma(a.y, mlog);
        float e2 = exp_fma(a.z, mlog), e3 = exp_fma(a.w, mlog);
        float e4 = exp_fma(b.x, mlog), e5 = exp_fma(b.y, mlog);
        float e6 = exp_fma(b.z, mlog), e7 = exp_fma(b.w, mlog);
        float t01 = e0 + e1, t23 = e2 + e3, t45 = e4 + e5, t67 = e6 + e7;
        float b2 = t45 + t67;
        float z8 = (t01 + t23) + b2;
        float b1 = t23 + t67;
        float b0 = (e1 + e3) + (e5 + e7);
        sb0 += b0; sb1 += b1; sb2 += b2; zt += z8;
        if (o & 1) so[0] += z8;
        if (o & 2) so[1] += z8;
        if (o & 4) so[2] += z8;
        if (o & 8) so[3] += z8;
    }

    // build per-thread s[0..14] (bit position order) + z at s[15]
    float s[16];
    s[0] = sb0; s[1] = sb1; s[2] = sb2;
#pragma unroll
    for (int pbit = 0; pbit < 8; ++pbit)
        s[3 + pbit] = ((tid >> pbit) & 1) ? zt : 0.f;
    s[11] = so[0]; s[12] = so[1]; s[13] = so[2]; s[14] = so[3];
    s[15] = zt;

    // block reduce (sum of 16 floats)
#pragma unroll
    for (int off = 16; off > 0; off >>= 1)
#pragma unroll
        for (int k = 0; k < 16; ++k)
            s[k] += __shfl_xor_sync(0xffffffffu, s[k], off);
    if (lane == 0)
#pragma unroll
        for (int k = 0; k < 16; ++k) sred[warp][k] = s[k];
    __syncthreads();
    if (tid < 16) {
        float v = 0.f;
#pragma unroll
        for (int w = 0; w < 8; ++w) v += sred[w][tid];
        sfin[tid] = v;
    }
    __syncthreads();
    if (tid < 15) {
        float Z = sfin[15];
        // output MSB-first: out[k] uses bit position 14-k
        out[(size_t)row * 15 + tid] = 2.f * sfin[14 - tid] / Z - 1.f;
    }
}

// ---------------------------------------------------------------------------
// launch
// ---------------------------------------------------------------------------
extern "C" void kernel_launch(void* const* d_in, const int* in_sizes, int n_in,
                              void* d_out, int out_size) {
    const int*   ids        = (const int*)d_in[0];
    const float* tensor     = (const float*)d_in[1];
    const float* weight     = (const float*)d_in[2];
    const float* weight_bit = (const float*)d_in[3];

    float* out     = (float*)d_out;
    float* id_emb  = out;
    float* bit_emb = id_emb + (size_t)ROWS * DIM;
    float* logit   = bit_emb + (size_t)ROWS * DIM;
    float* logit_w = logit + (size_t)ROWS * VOCAB;

    rowmax_init_kernel<<<ROWS / 256, 256>>>();
    embed_kernel<<<ROWS, 256>>>(ids, weight, weight_bit, id_emb, bit_emb);

    convertA_kernel<<<ROWS, 256>>>(tensor);
    convertB_kernel<<<VOCAB, 256>>>(weight);

    static bool attr_set = false;
    if (!attr_set) {
        cudaFuncSetAttribute(gemm_bf16_kernel,
                             cudaFuncAttributeMaxDynamicSharedMemorySize, GEMM_SMEM);
        attr_set = true;
    }
    dim3 grid(ROWS / BM, VOCAB / BN);   // (32, 250), m fastest for B reuse
    gemm_bf16_kernel<<<grid, GEMM_THREADS, GEMM_SMEM>>>(logit);

    softmax_bits_kernel<<<ROWS, 256>>>(logit, logit_w);
}